// round 14
// baseline (speedup 1.0000x reference)
#include <cuda_runtime.h>
#include <cuda_bf16.h>

#define NN 50000
#define EE 800000
// dims: IN=OUT=64, H=8, HD=8

// ---------------- device scratch (allocation-free) ----------------
__device__ float g_Q[NN * 64];
__device__ float g_K[NN * 64];
__device__ float g_V[NN * 64];
__device__ float g_sc[EE * 8];        // per-edge per-head exp score
__device__ float g_h1[NN * 64];       // pre-BN1 (x + attn@O_w + O_b)
__device__ float g_h2[NN * 64];       // pre-BN2 (bn1_out + ffn)
__device__ float g_stats[256];        // [sum1|sumsq1|sum2|sumsq2] x64
__device__ int   g_cnt[NN];
__device__ int   g_off[NN + 1];
__device__ int   g_cur[NN];
__device__ int   g_part[256];         // lookback scan state: [31:30]=state, [29:0]=sum
__device__ int   g_perm[EE];
// Fragment-packed bf16 hi/lo images of B = We^T for mma.sync m16n8k16:
// flat index = (((term*4 + kt)*8 + nt)*32 + lane)*2 + r
__device__ __align__(16) unsigned g_Bf[4096];

// ---------------- f32x2 helpers ----------------
__device__ __forceinline__ unsigned long long pack2(float v) {
    unsigned long long r;
    asm("mov.b64 %0, {%1, %1};" : "=l"(r) : "f"(v));
    return r;
}
__device__ __forceinline__ void fma2(unsigned long long& acc, unsigned long long a,
                                     unsigned long long b) {
    asm("fma.rn.f32x2 %0, %1, %2, %0;" : "+l"(acc) : "l"(a), "l"(b));
}
__device__ __forceinline__ float2 unpack2(unsigned long long v) {
    float2 r;
    asm("mov.b64 {%0, %1}, %2;" : "=f"(r.x), "=f"(r.y) : "l"(v));
    return r;
}

// ---------------- mma.sync helper (baseline PTX, no arch-specific features) -----
__device__ __forceinline__ void mma16816(float* d, unsigned a0, unsigned a1,
                                         unsigned a2, unsigned a3,
                                         unsigned b0, unsigned b1) {
    asm("mma.sync.aligned.m16n8k16.row.col.f32.bf16.bf16.f32 "
        "{%0,%1,%2,%3}, {%4,%5,%6,%7}, {%8,%9}, {%0,%1,%2,%3};"
        : "+f"(d[0]), "+f"(d[1]), "+f"(d[2]), "+f"(d[3])
        : "r"(a0), "r"(a1), "r"(a2), "r"(a3), "r"(b0), "r"(b1));
}
// Split float2 into packed bf16x2 hi (truncation) and lo (residual truncation)
__device__ __forceinline__ void split2(float2 v, unsigned& hi, unsigned& lo) {
    unsigned bx = __float_as_uint(v.x), by = __float_as_uint(v.y);
    hi = __byte_perm(bx, by, 0x7632);
    float hx = __uint_as_float(bx & 0xffff0000u);
    float hy = __uint_as_float(by & 0xffff0000u);
    lo = __byte_perm(__float_as_uint(v.x - hx), __float_as_uint(v.y - hy), 0x7632);
}

// Pair-swizzled weight staging (fp32 FFMA2 kernels)
__device__ __forceinline__ void stage_weight(float* sW, const float* W, int t, int nthr,
                                             int nrows) {
    const float4* W4 = (const float4*)W;
    float4* sW4 = (float4*)sW;
    for (int i = t; i < nrows * 16; i += nthr) {
        int k = i >> 4, q = i & 15;
        sW4[k * 16 + (q & 1) * 8 + (q >> 1)] = W4[i];
    }
}
__device__ __forceinline__ void stage_weight_half(float* sW, const float* W, int half,
                                                  int t, int nthr) {
    const float4* W4 = (const float4*)W;
    float4* sW4 = (float4*)sW;
    for (int i = t; i < 1024; i += nthr) {
        int k = i >> 4, q = i & 15;
        sW4[k * 16 + (q & 1) * 8 + (q >> 1)] = W4[k * 32 + half * 16 + q];
    }
}

// ---------------- generic 16-row warp-tile GEMM body (A from global) -------------
__device__ __forceinline__ void gemm16_body(const float* __restrict__ A, float* C,
                                            const float* sW, int tile, int t) {
    int warp = t >> 5, lane = t & 31;
    int lr = lane >> 3, lc = lane & 7;
    int tl = tile * 4 + warp;
    if (tl >= (NN + 15) / 16) return;
    int row0 = tl * 16 + lr * 4;
    const float4* A4 = (const float4*)A;
    const ulonglong2* sWu = (const ulonglong2*)sW;
    unsigned long long acc[4][4] = {};
    for (int kc = 0; kc < 64; kc += 4) {
        float4 a[4];
#pragma unroll
        for (int i = 0; i < 4; i++) {
            int r = row0 + i;
            a[i] = (r < NN) ? A4[r * 16 + (kc >> 2)] : make_float4(0, 0, 0, 0);
        }
#pragma unroll
        for (int kk = 0; kk < 4; kk++) {
            ulonglong2 wlo = sWu[(kc + kk) * 16 + lc];
            ulonglong2 whi = sWu[(kc + kk) * 16 + 8 + lc];
#pragma unroll
            for (int i = 0; i < 4; i++) {
                unsigned long long ax = pack2((&a[i].x)[kk]);
                fma2(acc[i][0], wlo.x, ax);
                fma2(acc[i][1], wlo.y, ax);
                fma2(acc[i][2], whi.x, ax);
                fma2(acc[i][3], whi.y, ax);
            }
        }
    }
#pragma unroll
    for (int i = 0; i < 4; i++) {
        int r = row0 + i;
        if (r < NN) {
            float2 c01 = unpack2(acc[i][0]), c23 = unpack2(acc[i][1]);
            float2 c45 = unpack2(acc[i][2]), c67 = unpack2(acc[i][3]);
            ((float4*)C)[r * 16 + lc * 2] = make_float4(c01.x, c01.y, c23.x, c23.y);
            ((float4*)C)[r * 16 + lc * 2 + 1] = make_float4(c45.x, c45.y, c67.x, c67.y);
        }
    }
}

// ---------------- 256-thread exclusive block scan ----------------
__device__ __forceinline__ int block_excl_scan_256(int v, int t, int* smem8) {
    unsigned lane = t & 31;
    int w = t >> 5;
    int x = v;
#pragma unroll
    for (int d = 1; d < 32; d <<= 1) {
        int y = __shfl_up_sync(0xffffffffu, x, d);
        if ((int)lane >= d) x += y;
    }
    if (lane == 31) smem8[w] = x;
    __syncthreads();
    if (t == 0) {
        int run = 0;
#pragma unroll
        for (int i = 0; i < 8; i++) { int c = smem8[i]; smem8[i] = run; run += c; }
    }
    __syncthreads();
    return x - v + smem8[w];
}

// -------- side #1: build B fragments + reset stats (1 block) --------------------
__global__ __launch_bounds__(256) void bf_kernel(const float* __restrict__ We) {
    int t = threadIdx.x;
    g_stats[t] = 0.0f;
    for (int i = t; i < 4096; i += 256) {
        int r = i & 1;
        int lane = (i >> 1) & 31;
        int nt = (i >> 6) & 7;
        int kt = (i >> 9) & 3;
        int term = (i >> 11) & 1;
        int gg = lane >> 2, tg = lane & 3;
        int n = nt * 8 + gg;
        int k0 = kt * 16 + 2 * tg + r * 8;
        float v0 = We[k0 * 64 + n];
        float v1 = We[(k0 + 1) * 64 + n];
        unsigned b0 = __float_as_uint(v0), b1 = __float_as_uint(v1);
        unsigned val;
        if (term == 0) {
            val = __byte_perm(b0, b1, 0x7632);
        } else {
            float h0 = __uint_as_float(b0 & 0xffff0000u);
            float h1 = __uint_as_float(b1 & 0xffff0000u);
            val = __byte_perm(__float_as_uint(v0 - h0), __float_as_uint(v1 - h1), 0x7632);
        }
        g_Bf[i] = val;
    }
}

// -------- side #2: V projection --------------------------------------------------
__global__ __launch_bounds__(128) void vproj_kernel(const float* __restrict__ x,
                                                    const float* __restrict__ Wv) {
    __shared__ float sW[4096];
    int t = threadIdx.x;
    stage_weight(sW, Wv, t, 128, 64);
    __syncthreads();
    gemm16_body(x, g_V, sW, blockIdx.x, t);
}

// -------- side #3: histogram dst degree + reset g_part ---------------------------
__global__ __launch_bounds__(256) void count_kernel(const int* __restrict__ ei) {
    int t = threadIdx.x;
    if (blockIdx.x == 0) g_part[t] = 0;
    int e = blockIdx.x * 256 + t;
    if (e < EE) atomicAdd(&g_cnt[ei[EE + e]], 1);
}

// -------- side #4: single-pass decoupled-lookback scan ---------------------------
__global__ __launch_bounds__(256) void scanlb_kernel() {
    __shared__ int s8[8];
    __shared__ int sTotal, sExc;
    int b = blockIdx.x, t = threadIdx.x;
    int i = b * 256 + t;
    int v = (i < NN) ? g_cnt[i] : 0;
    if (i < NN) g_cnt[i] = 0;   // reset for next graph replay
    int ex = block_excl_scan_256(v, t, s8);
    if (t == 255) sTotal = ex + v;
    __syncthreads();
    if (t == 0) {
        int total = sTotal;
        if (b == 0) {
            __threadfence();
            atomicExch(&g_part[0], (int)((2u << 30) | (unsigned)total));
            sExc = 0;
        } else {
            __threadfence();
            atomicExch(&g_part[b], (int)((1u << 30) | (unsigned)total));
            int running = 0;
            int look = b - 1;
            while (true) {
                unsigned w = (unsigned)atomicAdd(&g_part[look], 0);
                unsigned st = w >> 30;
                if (st == 0u) continue;
                running += (int)(w & 0x3fffffffu);
                if (st == 2u) break;
                look--;
            }
            __threadfence();
            atomicExch(&g_part[b], (int)((2u << 30) | (unsigned)(running + total)));
            sExc = running;
        }
    }
    __syncthreads();
    int off = ex + sExc;
    if (i < NN) { g_off[i] = off; g_cur[i] = off; }
    if (i == NN - 1) g_off[NN] = off + v;
}

// -------- side #5: bin edges by dst ----------------------------------------------
__global__ __launch_bounds__(256) void bin_kernel(const int* __restrict__ ei) {
    int e = blockIdx.x * 256 + threadIdx.x;
    if (e < EE) {
        int pos = atomicAdd(&g_cur[ei[EE + e]], 1);
        g_perm[pos] = e;
    }
}

// -------- main #1: Q/K projection; blockIdx.y = weight plane ---------------------
__global__ __launch_bounds__(128) void qk_kernel(const float* __restrict__ x,
                                                 const float* __restrict__ Wq,
                                                 const float* __restrict__ Wk) {
    __shared__ float sW[4096];
    int t = threadIdx.x;
    int wsel = blockIdx.y;
    const float* W = (wsel == 0) ? Wq : Wk;
    float* C = (wsel == 0) ? g_Q : g_K;
    stage_weight(sW, W, t, 128, 64);
    __syncthreads();
    gemm16_body(x, C, sW, blockIdx.x, t);
}

// -------- main #2 (profiled): mma.sync Eh GEMM, M-split, warp-private exchange ---
__global__ __launch_bounds__(128, 6) void score_tc_kernel(const float* __restrict__ EA,
                                                          const int* __restrict__ ei) {
    __shared__ __align__(16) uint2 sBf[2][4][8][32];   // [term][kt][nt][lane], 16KB
    __shared__ __align__(16) float sX[64 * 68];        // half exchange tile, 17KB
    int t = threadIdx.x;
    int wid = t >> 5, lane = t & 31;
    int g = lane >> 2, tg = lane & 3;
    int lr = lane >> 3, lc = lane & 7;
    // stage B fragments
    {
        const uint4* src4 = (const uint4*)g_Bf;
        uint4* dst4 = (uint4*)sBf;
#pragma unroll
        for (int i = 0; i < 8; i++) dst4[t + i * 128] = src4[t + i * 128];
    }
    __syncthreads();

    const float2* A2 = (const float2*)EA;
    const float4* K4 = (const float4*)g_K;
    const float4* Q4 = (const float4*)g_Q;
    const float inv = 0.35355339059327373f;  // 1/sqrt(8)
    int ebase = blockIdx.x * 128 + wid * 32;

#pragma unroll
    for (int grp = 0; grp < 2; grp++) {
        int r0 = ebase + grp * 16 + g;
        float d[8][4] = {};
#pragma unroll
        for (int kt = 0; kt < 4; kt++) {
            float2 a00 = A2[r0 * 32 + kt * 8 + tg];
            float2 a01 = A2[r0 * 32 + kt * 8 + tg + 4];
            float2 a10 = A2[(r0 + 8) * 32 + kt * 8 + tg];
            float2 a11 = A2[(r0 + 8) * 32 + kt * 8 + tg + 4];
            unsigned ah[4], al[4];
            split2(a00, ah[0], al[0]);
            split2(a10, ah[1], al[1]);
            split2(a01, ah[2], al[2]);
            split2(a11, ah[3], al[3]);
#pragma unroll
            for (int nt = 0; nt < 8; nt++) {
                uint2 bh = sBf[0][kt][nt][lane];
                uint2 bl = sBf[1][kt][nt][lane];
                mma16816(d[nt], ah[0], ah[1], ah[2], ah[3], bh.x, bh.y);
                mma16816(d[nt], ah[0], ah[1], ah[2], ah[3], bl.x, bl.y);
                mma16816(d[nt], al[0], al[1], al[2], al[3], bh.x, bh.y);
            }
        }
        // prefetch edge endpoints for this group's scoring (overlap with exchange)
        int esrc[4], edst[4];
#pragma unroll
        for (int i = 0; i < 4; i++) {
            int e = ebase + grp * 16 + lr * 4 + i;
            esrc[i] = ei[e];
            edst[i] = ei[EE + e];
        }
        __syncwarp();   // previous scoring reads of this warp's sX rows done
        // exchange: warp-private tile rows wid*16 + {g, g+8}
        {
            int ra = wid * 16 + g;
#pragma unroll
            for (int nt = 0; nt < 8; nt++) {
                *(float2*)&sX[ra * 68 + nt * 8 + 2 * tg] = make_float2(d[nt][0], d[nt][1]);
                *(float2*)&sX[(ra + 8) * 68 + nt * 8 + 2 * tg] = make_float2(d[nt][2], d[nt][3]);
            }
        }
        __syncwarp();
        // scoring: lane (lr,lc): 4 edge rows x head lc
#pragma unroll
        for (int i = 0; i < 4; i++) {
            int el = wid * 16 + lr * 4 + i;
            int e = ebase + grp * 16 + lr * 4 + i;
            float4 ea = *(const float4*)&sX[el * 68 + lc * 8];
            float4 eb = *(const float4*)&sX[el * 68 + lc * 8 + 4];
            float4 kk0 = K4[esrc[i] * 16 + lc * 2], kk1 = K4[esrc[i] * 16 + lc * 2 + 1];
            float4 qq0 = Q4[edst[i] * 16 + lc * 2], qq1 = Q4[edst[i] * 16 + lc * 2 + 1];
            float s = ea.x * kk0.x * qq0.x + ea.y * kk0.y * qq0.y
                    + ea.z * kk0.z * qq0.z + ea.w * kk0.w * qq0.w
                    + eb.x * kk1.x * qq1.x + eb.y * kk1.y * qq1.y
                    + eb.z * kk1.z * qq1.z + eb.w * kk1.w * qq1.w;
            s = fminf(fmaxf(s * inv, -5.0f), 5.0f);
            g_sc[e * 8 + lc] = __expf(s);
        }
        __syncwarp();
    }
}

// -------- main #3 (after join): FUSED agg + O-proj + residual + BN1 stats --------
// Warp per node. After shfl-reduction lanes 0..7 hold the node's 64-dim row;
// O-projection done in-warp: lane j -> cols 2j,2j+1 via broadcast shfls.
__global__ __launch_bounds__(256) void agg_fused_kernel(const int* __restrict__ ei,
                                                        const float* __restrict__ x,
                                                        const float* __restrict__ Ow,
                                                        const float* __restrict__ Ob) {
    __shared__ float sW[4096];       // Ow row-major (read as ull: row k, col pair j)
    __shared__ float ssum[64], ssq[64];
    int t = threadIdx.x;
    for (int i = t; i < 1024; i += 256)
        ((float4*)sW)[i] = ((const float4*)Ow)[i];
    if (t < 64) { ssum[t] = 0.0f; ssq[t] = 0.0f; }
    __syncthreads();
    int w = t >> 5, lane = t & 31;
    int lr = lane >> 3, lc = lane & 7;
    int n = blockIdx.x * 8 + w;   // grid 6250 * 8 = 50000 exactly
    int beg = g_off[n], end = g_off[n + 1];
    const float4* V4 = (const float4*)g_V;
    float acc[8] = {0, 0, 0, 0, 0, 0, 0, 0};
    float zacc = 0.0f;
    for (int i = beg + lr; i < end; i += 4) {
        int e = g_perm[i];
        int src = ei[e];
        float s = g_sc[e * 8 + lc];
        float4 v0 = V4[src * 16 + lc * 2];
        float4 v1 = V4[src * 16 + lc * 2 + 1];
        acc[0] += v0.x * s; acc[1] += v0.y * s; acc[2] += v0.z * s; acc[3] += v0.w * s;
        acc[4] += v1.x * s; acc[5] += v1.y * s; acc[6] += v1.z * s; acc[7] += v1.w * s;
        zacc += s;
    }
#pragma unroll
    for (int j = 0; j < 8; j++) {
        acc[j] += __shfl_xor_sync(0xffffffffu, acc[j], 8);
        acc[j] += __shfl_xor_sync(0xffffffffu, acc[j], 16);
    }
    zacc += __shfl_xor_sync(0xffffffffu, zacc, 8);
    zacc += __shfl_xor_sync(0xffffffffu, zacc, 16);
    float zi = 1.0f / (zacc + 1e-6f);
    float nv[8];
#pragma unroll
    for (int j = 0; j < 8; j++) nv[j] = acc[j] * zi;   // valid at lanes 0..7
    // O-projection: out[2*lane .. 2*lane+1] = nv_row @ Ow
    const unsigned long long* sWu = (const unsigned long long*)sW;
    unsigned long long o01 = 0ull;
#pragma unroll
    for (int k = 0; k < 64; k++) {
        float v = __shfl_sync(0xffffffffu, nv[k & 7], k >> 3);
        fma2(o01, sWu[k * 32 + lane], pack2(v));
    }
    float2 o = unpack2(o01);
    float2 ob = ((const float2*)Ob)[lane];
    float2 xr = ((const float2*)x)[n * 32 + lane];
    o.x += ob.x + xr.x;
    o.y += ob.y + xr.y;
    ((float2*)g_h1)[n * 32 + lane] = o;
    atomicAdd(&ssum[2 * lane], o.x);
    atomicAdd(&ssum[2 * lane + 1], o.y);
    atomicAdd(&ssq[2 * lane], o.x * o.x);
    atomicAdd(&ssq[2 * lane + 1], o.y * o.y);
    __syncthreads();
    if (t < 64) {
        atomicAdd(&g_stats[t], ssum[t]);
        atomicAdd(&g_stats[64 + t], ssq[t]);
    }
}

// -------- main #4: FUSED FFN: h2 = BN1h + (relu(BN1h@f1+b1))@f2 + b2 -------------
__global__ __launch_bounds__(128) void ffn_fused_kernel(const float* __restrict__ f1w,
                                                        const float* __restrict__ f1b,
                                                        const float* __restrict__ f2w,
                                                        const float* __restrict__ f2b,
                                                        const float* __restrict__ bn1g,
                                                        const float* __restrict__ bn1b) {
    __shared__ float sW1[2][4096];     // f1w swizzled halves, 32KB
    __shared__ float sT[16][132];      // hidden tile (padded rows)
    __shared__ float sH[16][68];       // BN1(h1) tile (padded rows)
    __shared__ float sScale[64], sShift[64], sB1[128], sF2b[64];
    __shared__ float ssum[64], ssq[64];
    int t = threadIdx.x;
    stage_weight_half(sW1[0], f1w, 0, t, 128);
    stage_weight_half(sW1[1], f1w, 1, t, 128);
    if (t < 64) {
        float mu = g_stats[t] * (1.0f / NN);
        float var = g_stats[64 + t] * (1.0f / NN) - mu * mu;
        float sc = bn1g[t] * rsqrtf(var + 1e-5f);
        sScale[t] = sc;
        sShift[t] = bn1b[t] - mu * sc;
        sF2b[t] = f2b[t];
        ssum[t] = 0.0f;
        ssq[t] = 0.0f;
    }
    if (t < 128) sB1[t] = f1b[t];
    __syncthreads();
    int row0 = blockIdx.x * 16;
#pragma unroll
    for (int ii = 0; ii < 8; ii++) {
        int idx = t + ii * 128;
        int rr = idx >> 6, c = idx & 63;
        float hv = g_h1[(row0 + rr) * 64 + c];
        sH[rr][c] = sScale[c] * hv + sShift[c];
    }
    __syncthreads();
    int w = t >> 5, lane = t & 31;
    int lr = lane >> 3, lc = lane & 7;
    int rh = w >> 1, ch = w & 1;
    int rb = rh * 8 + lr * 2;
    {
        const ulonglong2* sWu = (const ulonglong2*)sW1[ch];
        unsigned long long acc[2][4] = {};
        for (int kc = 0; kc < 64; kc += 4) {
            float4 a0 = *(const float4*)&sH[rb][kc];
            float4 a1 = *(const float4*)&sH[rb + 1][kc];
#pragma unroll
            for (int kk = 0; kk < 4; kk++) {
                ulonglong2 wlo = sWu[(kc + kk) * 16 + lc];
                ulonglong2 whi = sWu[(kc + kk) * 16 + 8 + lc];
                unsigned long long ax0 = pack2((&a0.x)[kk]);
                unsigned long long ax1 = pack2((&a1.x)[kk]);
                fma2(acc[0][0], wlo.x, ax0); fma2(acc[0][1], wlo.y, ax0);
                fma2(acc[0][2], whi.x, ax0); fma2(acc[0][3], whi.y, ax0);
                fma2(acc[1][0], wlo.x, ax1); fma2(acc[1][1], wlo.y, ax1);
                fma2(acc[1][2], whi.x, ax1); fma2(acc[1][3], whi.y, ax1);
            }
        }
        int j0 = ch * 64 + lc * 8;
        float4 b0 = *(const float4*)&sB1[j0];
        float4 b1 = *(const float4*)&sB1[j0 + 4];
#pragma unroll
        for (int i = 0; i < 2; i++) {
            float2 c01 = unpack2(acc[i][0]), c23 = unpack2(acc[i][1]);
            float2 c45 = unpack2(acc[i][2]), c67 = unpack2(acc[i][3]);
            float4 t0 = make_float4(fmaxf(c01.x + b0.x, 0.0f), fmaxf(c01.y + b0.y, 0.0f),
                                    fmaxf(c23.x + b0.z, 0.0f), fmaxf(c23.y + b0.w, 0.0f));
            float4 t1 = make_float4(fmaxf(c45.x + b1.x, 0.0f), fmaxf(c45.y + b1.y, 0.0f),
                                    fmaxf(c67.x + b1.z, 0.0f), fmaxf(c67.y + b1.w, 0.0f));
            *(float4*)&sT[rb + i][j0] = t0;
            *(float4*)&sT[rb + i][j0 + 4] = t1;
        }
    }
    __syncthreads();
    {
        int c4 = ch * 8 + lc;
        const ulonglong2* W2 = (const ulonglong2*)f2w;
        unsigned long long acc[2][2] = {};
        for (int kc = 0; kc < 128; kc += 4) {
            float4 a0 = *(const float4*)&sT[rb][kc];
            float4 a1 = *(const float4*)&sT[rb + 1][kc];
#pragma unroll
            for (int kk = 0; kk < 4; kk++) {
                ulonglong2 wv = W2[(kc + kk) * 16 + c4];
                unsigned long long ax0 = pack2((&a0.x)[kk]);
                unsigned long long ax1 = pack2((&a1.x)[kk]);
                fma2(acc[0][0], wv.x, ax0); fma2(acc[0][1], wv.y, ax0);
                fma2(acc[1][0], wv.x, ax1); fma2(acc[1][1], wv.y, ax1);
            }
        }
        int cb = c4 * 4;
        float2 fb0 = *(const float2*)&sF2b[cb];
        float2 fb1 = *(const float2*)&sF2b[cb + 2];
        float ls[4] = {0, 0, 0, 0}, lq[4] = {0, 0, 0, 0};
#pragma unroll
        for (int i = 0; i < 2; i++) {
            float2 c01 = unpack2(acc[i][0]), c23 = unpack2(acc[i][1]);
            float4 hres = *(const float4*)&sH[rb + i][cb];
            float4 o;
            o.x = c01.x + fb0.x + hres.x;
            o.y = c01.y + fb0.y + hres.y;
            o.z = c23.x + fb1.x + hres.z;
            o.w = c23.y + fb1.y + hres.w;
            *(float4*)&g_h2[(row0 + rb + i) * 64 + cb] = o;
            ls[0] += o.x; ls[1] += o.y; ls[2] += o.z; ls[3] += o.w;
            lq[0] += o.x * o.x; lq[1] += o.y * o.y;
            lq[2] += o.z * o.z; lq[3] += o.w * o.w;
        }
#pragma unroll
        for (int j = 0; j < 4; j++) {
            atomicAdd(&ssum[cb + j], ls[j]);
            atomicAdd(&ssq[cb + j], lq[j]);
        }
    }
    __syncthreads();
    if (t < 64) {
        atomicAdd(&g_stats[128 + t], ssum[t]);
        atomicAdd(&g_stats[192 + t], ssq[t]);
    }
}

// -------- main #5: BN2 apply -> output --------------------------------------------
__global__ __launch_bounds__(256) void bn2_kernel(const float* __restrict__ bn2g,
                                                  const float* __restrict__ bn2b,
                                                  float* __restrict__ out) {
    int tid = blockIdx.x * 256 + threadIdx.x;
    int i = tid & 15;
    int c0 = i * 4;
    float4 g = ((const float4*)bn2g)[i];
    float4 b = ((const float4*)bn2b)[i];
    float4 v = ((const float4*)g_h2)[tid];
    float4 o;
#pragma unroll
    for (int j = 0; j < 4; j++) {
        int c = c0 + j;
        float mu = g_stats[128 + c] * (1.0f / NN);
        float var = g_stats[192 + c] * (1.0f / NN) - mu * mu;
        float rs = rsqrtf(var + 1e-5f);
        (&o.x)[j] = (&g.x)[j] * ((&v.x)[j] - mu) * rs + (&b.x)[j];
    }
    ((float4*)out)[tid] = o;
}

// ---------------- host launcher (forked capture streams) ----------------
extern "C" void kernel_launch(void* const* d_in, const int* in_sizes, int n_in,
                              void* d_out, int out_size) {
    const float *x = nullptr, *edge_attr = nullptr;
    const float *Wq = nullptr, *Wk = nullptr, *We = nullptr, *Wv = nullptr, *Ow = nullptr;
    const float *Ob = nullptr, *f1w = nullptr, *f1b = nullptr, *f2w = nullptr, *f2b = nullptr;
    const float *bn1g = nullptr, *bn1b = nullptr, *bn2g = nullptr, *bn2b = nullptr;
    const int* ei = nullptr;
    int c4096 = 0, c8192 = 0, c64 = 0;
    for (int i = 0; i < n_in; i++) {
        int s = in_sizes[i];
        const void* p = d_in[i];
        if (s == NN * 64) x = (const float*)p;
        else if (s == EE * 64) edge_attr = (const float*)p;
        else if (s == 2 * EE) ei = (const int*)p;
        else if (s == 4096) {
            const float* f = (const float*)p;
            if (c4096 == 0) Wq = f;
            else if (c4096 == 1) Wk = f;
            else if (c4096 == 2) We = f;
            else if (c4096 == 3) Wv = f;
            else Ow = f;
            c4096++;
        } else if (s == 8192) {
            if (c8192 == 0) f1w = (const float*)p;
            else f2w = (const float*)p;
            c8192++;
        } else if (s == 128) {
            f1b = (const float*)p;
        } else if (s == 64) {
            const float* f = (const float*)p;
            if (c64 == 0) Ob = f;
            else if (c64 == 1) f2b = f;
            else if (c64 == 2) bn1g = f;
            else if (c64 == 3) bn1b = f;
            else if (c64 == 4) bn2g = f;
            else bn2b = f;
            c64++;
        }
    }

    static cudaStream_t s_side = nullptr;
    static cudaEvent_t s_ev0 = nullptr, s_evbf = nullptr, s_ev1 = nullptr;
    if (s_side == nullptr) {
        cudaStreamCreateWithFlags(&s_side, cudaStreamNonBlocking);
        cudaEventCreateWithFlags(&s_ev0, cudaEventDisableTiming);
        cudaEventCreateWithFlags(&s_evbf, cudaEventDisableTiming);
        cudaEventCreateWithFlags(&s_ev1, cudaEventDisableTiming);
    }

    // fork
    cudaEventRecord(s_ev0, 0);
    cudaStreamWaitEvent(s_side, s_ev0, 0);

    bf_kernel<<<1, 256, 0, s_side>>>(We);                       // #1 (side)
    cudaEventRecord(s_evbf, s_side);
    qk_kernel<<<dim3(782, 2), 128>>>(x, Wq, Wk);                // #2 (main)
    vproj_kernel<<<782, 128, 0, s_side>>>(x, Wv);               // #3 (side)
    cudaStreamWaitEvent(0, s_evbf, 0);                          // g_Bf ready
    score_tc_kernel<<<6250, 128>>>(edge_attr, ei);              // #4 (main) <- profiled
    count_kernel<<<(EE + 255) / 256, 256, 0, s_side>>>(ei);     // #5 (side)
    scanlb_kernel<<<196, 256, 0, s_side>>>();                   // #6 (side)
    bin_kernel<<<(EE + 255) / 256, 256, 0, s_side>>>(ei);       // #7 (side)
    cudaEventRecord(s_ev1, s_side);
    cudaStreamWaitEvent(0, s_ev1, 0);                           // V + CSR ready
    agg_fused_kernel<<<6250, 256>>>(ei, x, Ow, Ob);             // #8 (main)
    ffn_fused_kernel<<<3125, 128>>>(f1w, f1b, f2w, f2b, bn1g, bn1b);  // #9
    bn2_kernel<<<3125, 256>>>(bn2g, bn2b, (float*)d_out);       // #10
}

// round 15
// speedup vs baseline: 1.0354x; 1.0354x over previous
#include <cuda_runtime.h>
#include <cuda_bf16.h>

#define NN 50000
#define EE 800000
// dims: IN=OUT=64, H=8, HD=8

// ---------------- device scratch (allocation-free) ----------------
__device__ float g_Q[NN * 64];
__device__ float g_K[NN * 64];
__device__ float g_V[NN * 64];
__device__ float g_sc[EE * 8];        // per-edge per-head exp score
__device__ float g_h1[NN * 64];       // pre-BN1 (x + attn@O_w + O_b)
__device__ float g_h2[NN * 64];       // pre-BN2 (bn1_out + ffn)
__device__ float g_stats[256];        // [sum1|sumsq1|sum2|sumsq2] x64
__device__ int   g_cnt[NN];
__device__ int   g_off[NN + 1];
__device__ int   g_cur[NN];
__device__ int   g_part[256];         // lookback scan state: [31:30]=state, [29:0]=sum
__device__ int   g_perm[EE];
// Fragment-packed bf16 hi/lo images of B = We^T for mma.sync m16n8k16:
// flat index = (((term*4 + kt)*8 + nt)*32 + lane)*2 + r
__device__ __align__(16) unsigned g_Bf[4096];

// ---------------- f32x2 helpers ----------------
__device__ __forceinline__ unsigned long long pack2(float v) {
    unsigned long long r;
    asm("mov.b64 %0, {%1, %1};" : "=l"(r) : "f"(v));
    return r;
}
__device__ __forceinline__ void fma2(unsigned long long& acc, unsigned long long a,
                                     unsigned long long b) {
    asm("fma.rn.f32x2 %0, %1, %2, %0;" : "+l"(acc) : "l"(a), "l"(b));
}
__device__ __forceinline__ float2 unpack2(unsigned long long v) {
    float2 r;
    asm("mov.b64 {%0, %1}, %2;" : "=f"(r.x), "=f"(r.y) : "l"(v));
    return r;
}

// ---------------- mma.sync helper (baseline PTX, no arch-specific features) -----
__device__ __forceinline__ void mma16816(float* d, unsigned a0, unsigned a1,
                                         unsigned a2, unsigned a3,
                                         unsigned b0, unsigned b1) {
    asm("mma.sync.aligned.m16n8k16.row.col.f32.bf16.bf16.f32 "
        "{%0,%1,%2,%3}, {%4,%5,%6,%7}, {%8,%9}, {%0,%1,%2,%3};"
        : "+f"(d[0]), "+f"(d[1]), "+f"(d[2]), "+f"(d[3])
        : "r"(a0), "r"(a1), "r"(a2), "r"(a3), "r"(b0), "r"(b1));
}
// Split float2 into packed bf16x2 hi (truncation) and lo (residual truncation)
__device__ __forceinline__ void split2(float2 v, unsigned& hi, unsigned& lo) {
    unsigned bx = __float_as_uint(v.x), by = __float_as_uint(v.y);
    hi = __byte_perm(bx, by, 0x7632);
    float hx = __uint_as_float(bx & 0xffff0000u);
    float hy = __uint_as_float(by & 0xffff0000u);
    lo = __byte_perm(__float_as_uint(v.x - hx), __float_as_uint(v.y - hy), 0x7632);
}

// Pair-swizzled weight staging (fp32 FFMA2 kernels)
__device__ __forceinline__ void stage_weight(float* sW, const float* W, int t, int nthr,
                                             int nrows) {
    const float4* W4 = (const float4*)W;
    float4* sW4 = (float4*)sW;
    for (int i = t; i < nrows * 16; i += nthr) {
        int k = i >> 4, q = i & 15;
        sW4[k * 16 + (q & 1) * 8 + (q >> 1)] = W4[i];
    }
}
__device__ __forceinline__ void stage_weight_half(float* sW, const float* W, int half,
                                                  int t, int nthr) {
    const float4* W4 = (const float4*)W;
    float4* sW4 = (float4*)sW;
    for (int i = t; i < 1024; i += nthr) {
        int k = i >> 4, q = i & 15;
        sW4[k * 16 + (q & 1) * 8 + (q >> 1)] = W4[k * 32 + half * 16 + q];
    }
}

// ---------------- generic 16-row warp-tile GEMM body (A from global) -------------
__device__ __forceinline__ void gemm16_body(const float* __restrict__ A, float* C,
                                            const float* sW, int tile, int t) {
    int warp = t >> 5, lane = t & 31;
    int lr = lane >> 3, lc = lane & 7;
    int tl = tile * 4 + warp;
    if (tl >= (NN + 15) / 16) return;
    int row0 = tl * 16 + lr * 4;
    const float4* A4 = (const float4*)A;
    const ulonglong2* sWu = (const ulonglong2*)sW;
    unsigned long long acc[4][4] = {};
    for (int kc = 0; kc < 64; kc += 4) {
        float4 a[4];
#pragma unroll
        for (int i = 0; i < 4; i++) {
            int r = row0 + i;
            a[i] = (r < NN) ? A4[r * 16 + (kc >> 2)] : make_float4(0, 0, 0, 0);
        }
#pragma unroll
        for (int kk = 0; kk < 4; kk++) {
            ulonglong2 wlo = sWu[(kc + kk) * 16 + lc];
            ulonglong2 whi = sWu[(kc + kk) * 16 + 8 + lc];
#pragma unroll
            for (int i = 0; i < 4; i++) {
                unsigned long long ax = pack2((&a[i].x)[kk]);
                fma2(acc[i][0], wlo.x, ax);
                fma2(acc[i][1], wlo.y, ax);
                fma2(acc[i][2], whi.x, ax);
                fma2(acc[i][3], whi.y, ax);
            }
        }
    }
#pragma unroll
    for (int i = 0; i < 4; i++) {
        int r = row0 + i;
        if (r < NN) {
            float2 c01 = unpack2(acc[i][0]), c23 = unpack2(acc[i][1]);
            float2 c45 = unpack2(acc[i][2]), c67 = unpack2(acc[i][3]);
            ((float4*)C)[r * 16 + lc * 2] = make_float4(c01.x, c01.y, c23.x, c23.y);
            ((float4*)C)[r * 16 + lc * 2 + 1] = make_float4(c45.x, c45.y, c67.x, c67.y);
        }
    }
}

// ---------------- 256-thread exclusive block scan ----------------
__device__ __forceinline__ int block_excl_scan_256(int v, int t, int* smem8) {
    unsigned lane = t & 31;
    int w = t >> 5;
    int x = v;
#pragma unroll
    for (int d = 1; d < 32; d <<= 1) {
        int y = __shfl_up_sync(0xffffffffu, x, d);
        if ((int)lane >= d) x += y;
    }
    if (lane == 31) smem8[w] = x;
    __syncthreads();
    if (t == 0) {
        int run = 0;
#pragma unroll
        for (int i = 0; i < 8; i++) { int c = smem8[i]; smem8[i] = run; run += c; }
    }
    __syncthreads();
    return x - v + smem8[w];
}

// -------- side #1: build B fragments + reset stats (1 block) --------------------
__global__ __launch_bounds__(256) void bf_kernel(const float* __restrict__ We) {
    int t = threadIdx.x;
    g_stats[t] = 0.0f;
    for (int i = t; i < 4096; i += 256) {
        int r = i & 1;
        int lane = (i >> 1) & 31;
        int nt = (i >> 6) & 7;
        int kt = (i >> 9) & 3;
        int term = (i >> 11) & 1;
        int gg = lane >> 2, tg = lane & 3;
        int n = nt * 8 + gg;
        int k0 = kt * 16 + 2 * tg + r * 8;
        float v0 = We[k0 * 64 + n];
        float v1 = We[(k0 + 1) * 64 + n];
        unsigned b0 = __float_as_uint(v0), b1 = __float_as_uint(v1);
        unsigned val;
        if (term == 0) {
            val = __byte_perm(b0, b1, 0x7632);
        } else {
            float h0 = __uint_as_float(b0 & 0xffff0000u);
            float h1 = __uint_as_float(b1 & 0xffff0000u);
            val = __byte_perm(__float_as_uint(v0 - h0), __float_as_uint(v1 - h1), 0x7632);
        }
        g_Bf[i] = val;
    }
}

// -------- side #2: V projection --------------------------------------------------
__global__ __launch_bounds__(128) void vproj_kernel(const float* __restrict__ x,
                                                    const float* __restrict__ Wv) {
    __shared__ float sW[4096];
    int t = threadIdx.x;
    stage_weight(sW, Wv, t, 128, 64);
    __syncthreads();
    gemm16_body(x, g_V, sW, blockIdx.x, t);
}

// -------- side #3: histogram dst degree + reset g_part ---------------------------
__global__ __launch_bounds__(256) void count_kernel(const int* __restrict__ ei) {
    int t = threadIdx.x;
    if (blockIdx.x == 0) g_part[t] = 0;
    int e = blockIdx.x * 256 + t;
    if (e < EE) atomicAdd(&g_cnt[ei[EE + e]], 1);
}

// -------- side #4: single-pass decoupled-lookback scan ---------------------------
__global__ __launch_bounds__(256) void scanlb_kernel() {
    __shared__ int s8[8];
    __shared__ int sTotal, sExc;
    int b = blockIdx.x, t = threadIdx.x;
    int i = b * 256 + t;
    int v = (i < NN) ? g_cnt[i] : 0;
    if (i < NN) g_cnt[i] = 0;   // reset for next graph replay
    int ex = block_excl_scan_256(v, t, s8);
    if (t == 255) sTotal = ex + v;
    __syncthreads();
    if (t == 0) {
        int total = sTotal;
        if (b == 0) {
            __threadfence();
            atomicExch(&g_part[0], (int)((2u << 30) | (unsigned)total));
            sExc = 0;
        } else {
            __threadfence();
            atomicExch(&g_part[b], (int)((1u << 30) | (unsigned)total));
            int running = 0;
            int look = b - 1;
            while (true) {
                unsigned w = (unsigned)atomicAdd(&g_part[look], 0);
                unsigned st = w >> 30;
                if (st == 0u) continue;
                running += (int)(w & 0x3fffffffu);
                if (st == 2u) break;
                look--;
            }
            __threadfence();
            atomicExch(&g_part[b], (int)((2u << 30) | (unsigned)(running + total)));
            sExc = running;
        }
    }
    __syncthreads();
    int off = ex + sExc;
    if (i < NN) { g_off[i] = off; g_cur[i] = off; }
    if (i == NN - 1) g_off[NN] = off + v;
}

// -------- side #5: bin edges by dst ----------------------------------------------
__global__ __launch_bounds__(256) void bin_kernel(const int* __restrict__ ei) {
    int e = blockIdx.x * 256 + threadIdx.x;
    if (e < EE) {
        int pos = atomicAdd(&g_cur[ei[EE + e]], 1);
        g_perm[pos] = e;
    }
}

// -------- main #1: Q/K projection; blockIdx.y = weight plane ---------------------
__global__ __launch_bounds__(128) void qk_kernel(const float* __restrict__ x,
                                                 const float* __restrict__ Wq,
                                                 const float* __restrict__ Wk) {
    __shared__ float sW[4096];
    int t = threadIdx.x;
    int wsel = blockIdx.y;
    const float* W = (wsel == 0) ? Wq : Wk;
    float* C = (wsel == 0) ? g_Q : g_K;
    stage_weight(sW, W, t, 128, 64);
    __syncthreads();
    gemm16_body(x, C, sW, blockIdx.x, t);
}

// -------- main #2 (profiled): mma.sync Eh GEMM, M-split, warp-private exchange ---
__global__ __launch_bounds__(128) void score_tc_kernel(const float* __restrict__ EA,
                                                       const int* __restrict__ ei) {
    __shared__ __align__(16) uint2 sBf[2][4][8][32];   // [term][kt][nt][lane], 16KB
    __shared__ __align__(16) float sX[64 * 68];        // half exchange tile, 17KB
    int t = threadIdx.x;
    int wid = t >> 5, lane = t & 31;
    int g = lane >> 2, tg = lane & 3;
    int lr = lane >> 3, lc = lane & 7;
    // stage B fragments
    {
        const uint4* src4 = (const uint4*)g_Bf;
        uint4* dst4 = (uint4*)sBf;
#pragma unroll
        for (int i = 0; i < 8; i++) dst4[t + i * 128] = src4[t + i * 128];
    }
    __syncthreads();

    const float2* A2 = (const float2*)EA;
    const float4* K4 = (const float4*)g_K;
    const float4* Q4 = (const float4*)g_Q;
    const float inv = 0.35355339059327373f;  // 1/sqrt(8)
    int ebase = blockIdx.x * 128 + wid * 32;

#pragma unroll
    for (int grp = 0; grp < 2; grp++) {
        int r0 = ebase + grp * 16 + g;
        float d[8][4] = {};
#pragma unroll
        for (int kt = 0; kt < 4; kt++) {
            float2 a00 = A2[r0 * 32 + kt * 8 + tg];
            float2 a01 = A2[r0 * 32 + kt * 8 + tg + 4];
            float2 a10 = A2[(r0 + 8) * 32 + kt * 8 + tg];
            float2 a11 = A2[(r0 + 8) * 32 + kt * 8 + tg + 4];
            unsigned ah[4], al[4];
            split2(a00, ah[0], al[0]);
            split2(a10, ah[1], al[1]);
            split2(a01, ah[2], al[2]);
            split2(a11, ah[3], al[3]);
#pragma unroll
            for (int nt = 0; nt < 8; nt++) {
                uint2 bh = sBf[0][kt][nt][lane];
                uint2 bl = sBf[1][kt][nt][lane];
                mma16816(d[nt], ah[0], ah[1], ah[2], ah[3], bh.x, bh.y);
                mma16816(d[nt], ah[0], ah[1], ah[2], ah[3], bl.x, bl.y);
                mma16816(d[nt], al[0], al[1], al[2], al[3], bh.x, bh.y);
            }
        }
        // prefetch edge endpoints for this group's scoring (overlap with exchange)
        int esrc[4], edst[4];
#pragma unroll
        for (int i = 0; i < 4; i++) {
            int e = ebase + grp * 16 + lr * 4 + i;
            esrc[i] = ei[e];
            edst[i] = ei[EE + e];
        }
        __syncwarp();   // previous scoring reads of this warp's sX rows done
        // exchange: warp-private tile rows wid*16 + {g, g+8}
        {
            int ra = wid * 16 + g;
#pragma unroll
            for (int nt = 0; nt < 8; nt++) {
                *(float2*)&sX[ra * 68 + nt * 8 + 2 * tg] = make_float2(d[nt][0], d[nt][1]);
                *(float2*)&sX[(ra + 8) * 68 + nt * 8 + 2 * tg] = make_float2(d[nt][2], d[nt][3]);
            }
        }
        __syncwarp();
        // scoring: lane (lr,lc): 4 edge rows x head lc
#pragma unroll
        for (int i = 0; i < 4; i++) {
            int el = wid * 16 + lr * 4 + i;
            int e = ebase + grp * 16 + lr * 4 + i;
            float4 ea = *(const float4*)&sX[el * 68 + lc * 8];
            float4 eb = *(const float4*)&sX[el * 68 + lc * 8 + 4];
            float4 kk0 = K4[esrc[i] * 16 + lc * 2], kk1 = K4[esrc[i] * 16 + lc * 2 + 1];
            float4 qq0 = Q4[edst[i] * 16 + lc * 2], qq1 = Q4[edst[i] * 16 + lc * 2 + 1];
            float s = ea.x * kk0.x * qq0.x + ea.y * kk0.y * qq0.y
                    + ea.z * kk0.z * qq0.z + ea.w * kk0.w * qq0.w
                    + eb.x * kk1.x * qq1.x + eb.y * kk1.y * qq1.y
                    + eb.z * kk1.z * qq1.z + eb.w * kk1.w * qq1.w;
            s = fminf(fmaxf(s * inv, -5.0f), 5.0f);
            g_sc[e * 8 + lc] = __expf(s);
        }
        __syncwarp();
    }
}

// -------- main #3 (after join): FUSED agg + O-proj + residual + BN1 stats --------
__global__ __launch_bounds__(256) void agg_fused_kernel(const int* __restrict__ ei,
                                                        const float* __restrict__ x,
                                                        const float* __restrict__ Ow,
                                                        const float* __restrict__ Ob) {
    __shared__ float sW[4096];       // Ow row-major
    __shared__ float ssum[64], ssq[64];
    int t = threadIdx.x;
    for (int i = t; i < 1024; i += 256)
        ((float4*)sW)[i] = ((const float4*)Ow)[i];
    if (t < 64) { ssum[t] = 0.0f; ssq[t] = 0.0f; }
    __syncthreads();
    int w = t >> 5, lane = t & 31;
    int lr = lane >> 3, lc = lane & 7;
    int n = blockIdx.x * 8 + w;   // grid 6250 * 8 = 50000 exactly
    int beg = g_off[n], end = g_off[n + 1];
    const float4* V4 = (const float4*)g_V;
    float acc[8] = {0, 0, 0, 0, 0, 0, 0, 0};
    float zacc = 0.0f;
    for (int i = beg + lr; i < end; i += 4) {
        int e = g_perm[i];
        int src = ei[e];
        float s = g_sc[e * 8 + lc];
        float4 v0 = V4[src * 16 + lc * 2];
        float4 v1 = V4[src * 16 + lc * 2 + 1];
        acc[0] += v0.x * s; acc[1] += v0.y * s; acc[2] += v0.z * s; acc[3] += v0.w * s;
        acc[4] += v1.x * s; acc[5] += v1.y * s; acc[6] += v1.z * s; acc[7] += v1.w * s;
        zacc += s;
    }
#pragma unroll
    for (int j = 0; j < 8; j++) {
        acc[j] += __shfl_xor_sync(0xffffffffu, acc[j], 8);
        acc[j] += __shfl_xor_sync(0xffffffffu, acc[j], 16);
    }
    zacc += __shfl_xor_sync(0xffffffffu, zacc, 8);
    zacc += __shfl_xor_sync(0xffffffffu, zacc, 16);
    float zi = 1.0f / (zacc + 1e-6f);
    float nv[8];
#pragma unroll
    for (int j = 0; j < 8; j++) nv[j] = acc[j] * zi;   // valid at lanes 0..7
    // O-projection: out[2*lane .. 2*lane+1] = nv_row @ Ow
    const unsigned long long* sWu = (const unsigned long long*)sW;
    unsigned long long o01 = 0ull;
#pragma unroll
    for (int k = 0; k < 64; k++) {
        float v = __shfl_sync(0xffffffffu, nv[k & 7], k >> 3);
        fma2(o01, sWu[k * 32 + lane], pack2(v));
    }
    float2 o = unpack2(o01);
    float2 ob = ((const float2*)Ob)[lane];
    float2 xr = ((const float2*)x)[n * 32 + lane];
    o.x += ob.x + xr.x;
    o.y += ob.y + xr.y;
    ((float2*)g_h1)[n * 32 + lane] = o;
    atomicAdd(&ssum[2 * lane], o.x);
    atomicAdd(&ssum[2 * lane + 1], o.y);
    atomicAdd(&ssq[2 * lane], o.x * o.x);
    atomicAdd(&ssq[2 * lane + 1], o.y * o.y);
    __syncthreads();
    if (t < 64) {
        atomicAdd(&g_stats[t], ssum[t]);
        atomicAdd(&g_stats[64 + t], ssq[t]);
    }
}

// -------- main #4: FUSED FFN: h2 = BN1h + (relu(BN1h@f1+b1))@f2 + b2 -------------
__global__ __launch_bounds__(128) void ffn_fused_kernel(const float* __restrict__ f1w,
                                                        const float* __restrict__ f1b,
                                                        const float* __restrict__ f2w,
                                                        const float* __restrict__ f2b,
                                                        const float* __restrict__ bn1g,
                                                        const float* __restrict__ bn1b) {
    __shared__ float sW1[2][4096];     // f1w swizzled halves, 32KB
    __shared__ float sT[16][132];      // hidden tile (padded rows)
    __shared__ float sH[16][68];       // BN1(h1) tile (padded rows)
    __shared__ float sScale[64], sShift[64], sB1[128], sF2b[64];
    __shared__ float ssum[64], ssq[64];
    int t = threadIdx.x;
    stage_weight_half(sW1[0], f1w, 0, t, 128);
    stage_weight_half(sW1[1], f1w, 1, t, 128);
    if (t < 64) {
        float mu = g_stats[t] * (1.0f / NN);
        float var = g_stats[64 + t] * (1.0f / NN) - mu * mu;
        float sc = bn1g[t] * rsqrtf(var + 1e-5f);
        sScale[t] = sc;
        sShift[t] = bn1b[t] - mu * sc;
        sF2b[t] = f2b[t];
        ssum[t] = 0.0f;
        ssq[t] = 0.0f;
    }
    if (t < 128) sB1[t] = f1b[t];
    __syncthreads();
    int row0 = blockIdx.x * 16;
#pragma unroll
    for (int ii = 0; ii < 8; ii++) {
        int idx = t + ii * 128;
        int rr = idx >> 6, c = idx & 63;
        float hv = g_h1[(row0 + rr) * 64 + c];
        sH[rr][c] = sScale[c] * hv + sShift[c];
    }
    __syncthreads();
    int w = t >> 5, lane = t & 31;
    int lr = lane >> 3, lc = lane & 7;
    int rh = w >> 1, ch = w & 1;
    int rb = rh * 8 + lr * 2;
    {
        const ulonglong2* sWu = (const ulonglong2*)sW1[ch];
        unsigned long long acc[2][4] = {};
        for (int kc = 0; kc < 64; kc += 4) {
            float4 a0 = *(const float4*)&sH[rb][kc];
            float4 a1 = *(const float4*)&sH[rb + 1][kc];
#pragma unroll
            for (int kk = 0; kk < 4; kk++) {
                ulonglong2 wlo = sWu[(kc + kk) * 16 + lc];
                ulonglong2 whi = sWu[(kc + kk) * 16 + 8 + lc];
                unsigned long long ax0 = pack2((&a0.x)[kk]);
                unsigned long long ax1 = pack2((&a1.x)[kk]);
                fma2(acc[0][0], wlo.x, ax0); fma2(acc[0][1], wlo.y, ax0);
                fma2(acc[0][2], whi.x, ax0); fma2(acc[0][3], whi.y, ax0);
                fma2(acc[1][0], wlo.x, ax1); fma2(acc[1][1], wlo.y, ax1);
                fma2(acc[1][2], whi.x, ax1); fma2(acc[1][3], whi.y, ax1);
            }
        }
        int j0 = ch * 64 + lc * 8;
        float4 b0 = *(const float4*)&sB1[j0];
        float4 b1 = *(const float4*)&sB1[j0 + 4];
#pragma unroll
        for (int i = 0; i < 2; i++) {
            float2 c01 = unpack2(acc[i][0]), c23 = unpack2(acc[i][1]);
            float2 c45 = unpack2(acc[i][2]), c67 = unpack2(acc[i][3]);
            float4 t0 = make_float4(fmaxf(c01.x + b0.x, 0.0f), fmaxf(c01.y + b0.y, 0.0f),
                                    fmaxf(c23.x + b0.z, 0.0f), fmaxf(c23.y + b0.w, 0.0f));
            float4 t1 = make_float4(fmaxf(c45.x + b1.x, 0.0f), fmaxf(c45.y + b1.y, 0.0f),
                                    fmaxf(c67.x + b1.z, 0.0f), fmaxf(c67.y + b1.w, 0.0f));
            *(float4*)&sT[rb + i][j0] = t0;
            *(float4*)&sT[rb + i][j0 + 4] = t1;
        }
    }
    __syncthreads();
    {
        int c4 = ch * 8 + lc;
        const ulonglong2* W2 = (const ulonglong2*)f2w;
        unsigned long long acc[2][2] = {};
        for (int kc = 0; kc < 128; kc += 4) {
            float4 a0 = *(const float4*)&sT[rb][kc];
            float4 a1 = *(const float4*)&sT[rb + 1][kc];
#pragma unroll
            for (int kk = 0; kk < 4; kk++) {
                ulonglong2 wv = W2[(kc + kk) * 16 + c4];
                unsigned long long ax0 = pack2((&a0.x)[kk]);
                unsigned long long ax1 = pack2((&a1.x)[kk]);
                fma2(acc[0][0], wv.x, ax0); fma2(acc[0][1], wv.y, ax0);
                fma2(acc[1][0], wv.x, ax1); fma2(acc[1][1], wv.y, ax1);
            }
        }
        int cb = c4 * 4;
        float2 fb0 = *(const float2*)&sF2b[cb];
        float2 fb1 = *(const float2*)&sF2b[cb + 2];
        float ls[4] = {0, 0, 0, 0}, lq[4] = {0, 0, 0, 0};
#pragma unroll
        for (int i = 0; i < 2; i++) {
            float2 c01 = unpack2(acc[i][0]), c23 = unpack2(acc[i][1]);
            float4 hres = *(const float4*)&sH[rb + i][cb];
            float4 o;
            o.x = c01.x + fb0.x + hres.x;
            o.y = c01.y + fb0.y + hres.y;
            o.z = c23.x + fb1.x + hres.z;
            o.w = c23.y + fb1.y + hres.w;
            *(float4*)&g_h2[(row0 + rb + i) * 64 + cb] = o;
            ls[0] += o.x; ls[1] += o.y; ls[2] += o.z; ls[3] += o.w;
            lq[0] += o.x * o.x; lq[1] += o.y * o.y;
            lq[2] += o.z * o.z; lq[3] += o.w * o.w;
        }
#pragma unroll
        for (int j = 0; j < 4; j++) {
            atomicAdd(&ssum[cb + j], ls[j]);
            atomicAdd(&ssq[cb + j], lq[j]);
        }
    }
    __syncthreads();
    if (t < 64) {
        atomicAdd(&g_stats[128 + t], ssum[t]);
        atomicAdd(&g_stats[192 + t], ssq[t]);
    }
}

// -------- main #5: BN2 apply -> output --------------------------------------------
__global__ __launch_bounds__(256) void bn2_kernel(const float* __restrict__ bn2g,
                                                  const float* __restrict__ bn2b,
                                                  float* __restrict__ out) {
    int tid = blockIdx.x * 256 + threadIdx.x;
    int i = tid & 15;
    int c0 = i * 4;
    float4 g = ((const float4*)bn2g)[i];
    float4 b = ((const float4*)bn2b)[i];
    float4 v = ((const float4*)g_h2)[tid];
    float4 o;
#pragma unroll
    for (int j = 0; j < 4; j++) {
        int c = c0 + j;
        float mu = g_stats[128 + c] * (1.0f / NN);
        float var = g_stats[192 + c] * (1.0f / NN) - mu * mu;
        float rs = rsqrtf(var + 1e-5f);
        (&o.x)[j] = (&g.x)[j] * ((&v.x)[j] - mu) * rs + (&b.x)[j];
    }
    ((float4*)out)[tid] = o;
}

// ---------------- host launcher (forked capture streams) ----------------
extern "C" void kernel_launch(void* const* d_in, const int* in_sizes, int n_in,
                              void* d_out, int out_size) {
    const float *x = nullptr, *edge_attr = nullptr;
    const float *Wq = nullptr, *Wk = nullptr, *We = nullptr, *Wv = nullptr, *Ow = nullptr;
    const float *Ob = nullptr, *f1w = nullptr, *f1b = nullptr, *f2w = nullptr, *f2b = nullptr;
    const float *bn1g = nullptr, *bn1b = nullptr, *bn2g = nullptr, *bn2b = nullptr;
    const int* ei = nullptr;
    int c4096 = 0, c8192 = 0, c64 = 0;
    for (int i = 0; i < n_in; i++) {
        int s = in_sizes[i];
        const void* p = d_in[i];
        if (s == NN * 64) x = (const float*)p;
        else if (s == EE * 64) edge_attr = (const float*)p;
        else if (s == 2 * EE) ei = (const int*)p;
        else if (s == 4096) {
            const float* f = (const float*)p;
            if (c4096 == 0) Wq = f;
            else if (c4096 == 1) Wk = f;
            else if (c4096 == 2) We = f;
            else if (c4096 == 3) Wv = f;
            else Ow = f;
            c4096++;
        } else if (s == 8192) {
            if (c8192 == 0) f1w = (const float*)p;
            else f2w = (const float*)p;
            c8192++;
        } else if (s == 128) {
            f1b = (const float*)p;
        } else if (s == 64) {
            const float* f = (const float*)p;
            if (c64 == 0) Ob = f;
            else if (c64 == 1) f2b = f;
            else if (c64 == 2) bn1g = f;
            else if (c64 == 3) bn1b = f;
            else if (c64 == 4) bn2g = f;
            else bn2b = f;
            c64++;
        }
    }

    static cudaStream_t s_side = nullptr;
    static cudaEvent_t s_ev0 = nullptr, s_evbf = nullptr, s_ev1 = nullptr;
    if (s_side == nullptr) {
        cudaStreamCreateWithFlags(&s_side, cudaStreamNonBlocking);
        cudaEventCreateWithFlags(&s_ev0, cudaEventDisableTiming);
        cudaEventCreateWithFlags(&s_evbf, cudaEventDisableTiming);
        cudaEventCreateWithFlags(&s_ev1, cudaEventDisableTiming);
    }

    // fork
    cudaEventRecord(s_ev0, 0);
    cudaStreamWaitEvent(s_side, s_ev0, 0);

    bf_kernel<<<1, 256, 0, s_side>>>(We);                       // #1 (side)
    cudaEventRecord(s_evbf, s_side);
    qk_kernel<<<dim3(782, 2), 128>>>(x, Wq, Wk);                // #2 (main)
    vproj_kernel<<<782, 128, 0, s_side>>>(x, Wv);               // #3 (side)
    cudaStreamWaitEvent(0, s_evbf, 0);                          // g_Bf ready
    score_tc_kernel<<<6250, 128>>>(edge_attr, ei);              // #4 (main) <- profiled
    count_kernel<<<(EE + 255) / 256, 256, 0, s_side>>>(ei);     // #5 (side)
    scanlb_kernel<<<196, 256, 0, s_side>>>();                   // #6 (side)
    bin_kernel<<<(EE + 255) / 256, 256, 0, s_side>>>(ei);       // #7 (side)
    cudaEventRecord(s_ev1, s_side);
    cudaStreamWaitEvent(0, s_ev1, 0);                           // V + CSR ready
    agg_fused_kernel<<<6250, 256>>>(ei, x, Ow, Ob);             // #8 (main)
    ffn_fused_kernel<<<3125, 128>>>(f1w, f1b, f2w, f2b, bn1g, bn1b);  // #9
    bn2_kernel<<<3125, 256>>>(bn2g, bn2b, (float*)d_out);       // #10
}

// round 16
// speedup vs baseline: 1.0928x; 1.0555x over previous
#include <cuda_runtime.h>
#include <cuda_bf16.h>

#define NN 50000
#define EE 800000
// dims: IN=OUT=64, H=8, HD=8

// ---------------- device scratch (allocation-free) ----------------
__device__ float g_Q[NN * 64];
__device__ float g_K[NN * 64];
__device__ float g_V[NN * 64];
__device__ float g_wV[NN * 64];       // normalized attn output (written once by agg)
__device__ float g_sc[EE * 8];        // per-edge per-head exp score
__device__ float g_h1[NN * 64];       // pre-BN1 (x + attn@O_w + O_b)
__device__ float g_h2[NN * 64];       // pre-BN2 (bn1_out + ffn)
__device__ float g_stats[256];        // [sum1|sumsq1|sum2|sumsq2] x64
__device__ int   g_cnt[NN];
__device__ int   g_off[NN + 1];
__device__ int   g_cur[NN];
__device__ int   g_part[256];         // lookback scan state: [31:30]=state, [29:0]=sum
__device__ int   g_perm[EE];
// Fragment-packed bf16 hi/lo images of B = We^T for mma.sync m16n8k16:
// flat index = (((term*4 + kt)*8 + nt)*32 + lane)*2 + r
__device__ __align__(16) unsigned g_Bf[4096];

// ---------------- f32x2 helpers ----------------
__device__ __forceinline__ unsigned long long pack2(float v) {
    unsigned long long r;
    asm("mov.b64 %0, {%1, %1};" : "=l"(r) : "f"(v));
    return r;
}
__device__ __forceinline__ void fma2(unsigned long long& acc, unsigned long long a,
                                     unsigned long long b) {
    asm("fma.rn.f32x2 %0, %1, %2, %0;" : "+l"(acc) : "l"(a), "l"(b));
}
__device__ __forceinline__ float2 unpack2(unsigned long long v) {
    float2 r;
    asm("mov.b64 {%0, %1}, %2;" : "=f"(r.x), "=f"(r.y) : "l"(v));
    return r;
}

// ---------------- mma.sync helper (baseline PTX, no arch-specific features) -----
__device__ __forceinline__ void mma16816(float* d, unsigned a0, unsigned a1,
                                         unsigned a2, unsigned a3,
                                         unsigned b0, unsigned b1) {
    asm("mma.sync.aligned.m16n8k16.row.col.f32.bf16.bf16.f32 "
        "{%0,%1,%2,%3}, {%4,%5,%6,%7}, {%8,%9}, {%0,%1,%2,%3};"
        : "+f"(d[0]), "+f"(d[1]), "+f"(d[2]), "+f"(d[3])
        : "r"(a0), "r"(a1), "r"(a2), "r"(a3), "r"(b0), "r"(b1));
}
// Split float2 into packed bf16x2 hi (truncation) and lo (residual truncation)
__device__ __forceinline__ void split2(float2 v, unsigned& hi, unsigned& lo) {
    unsigned bx = __float_as_uint(v.x), by = __float_as_uint(v.y);
    hi = __byte_perm(bx, by, 0x7632);
    float hx = __uint_as_float(bx & 0xffff0000u);
    float hy = __uint_as_float(by & 0xffff0000u);
    lo = __byte_perm(__float_as_uint(v.x - hx), __float_as_uint(v.y - hy), 0x7632);
}

// Pair-swizzled weight staging (fp32 FFMA2 kernels)
__device__ __forceinline__ void stage_weight(float* sW, const float* W, int t, int nthr,
                                             int nrows) {
    const float4* W4 = (const float4*)W;
    float4* sW4 = (float4*)sW;
    for (int i = t; i < nrows * 16; i += nthr) {
        int k = i >> 4, q = i & 15;
        sW4[k * 16 + (q & 1) * 8 + (q >> 1)] = W4[i];
    }
}
__device__ __forceinline__ void stage_weight_half(float* sW, const float* W, int half,
                                                  int t, int nthr) {
    const float4* W4 = (const float4*)W;
    float4* sW4 = (float4*)sW;
    for (int i = t; i < 1024; i += nthr) {
        int k = i >> 4, q = i & 15;
        sW4[k * 16 + (q & 1) * 8 + (q >> 1)] = W4[k * 32 + half * 16 + q];
    }
}

// ---------------- generic 16-row warp-tile GEMM body (A from global) -------------
__device__ __forceinline__ void gemm16_body(const float* __restrict__ A, float* C,
                                            const float* sW, int tile, int t) {
    int warp = t >> 5, lane = t & 31;
    int lr = lane >> 3, lc = lane & 7;
    int tl = tile * 4 + warp;
    if (tl >= (NN + 15) / 16) return;
    int row0 = tl * 16 + lr * 4;
    const float4* A4 = (const float4*)A;
    const ulonglong2* sWu = (const ulonglong2*)sW;
    unsigned long long acc[4][4] = {};
    for (int kc = 0; kc < 64; kc += 4) {
        float4 a[4];
#pragma unroll
        for (int i = 0; i < 4; i++) {
            int r = row0 + i;
            a[i] = (r < NN) ? A4[r * 16 + (kc >> 2)] : make_float4(0, 0, 0, 0);
        }
#pragma unroll
        for (int kk = 0; kk < 4; kk++) {
            ulonglong2 wlo = sWu[(kc + kk) * 16 + lc];
            ulonglong2 whi = sWu[(kc + kk) * 16 + 8 + lc];
#pragma unroll
            for (int i = 0; i < 4; i++) {
                unsigned long long ax = pack2((&a[i].x)[kk]);
                fma2(acc[i][0], wlo.x, ax);
                fma2(acc[i][1], wlo.y, ax);
                fma2(acc[i][2], whi.x, ax);
                fma2(acc[i][3], whi.y, ax);
            }
        }
    }
#pragma unroll
    for (int i = 0; i < 4; i++) {
        int r = row0 + i;
        if (r < NN) {
            float2 c01 = unpack2(acc[i][0]), c23 = unpack2(acc[i][1]);
            float2 c45 = unpack2(acc[i][2]), c67 = unpack2(acc[i][3]);
            ((float4*)C)[r * 16 + lc * 2] = make_float4(c01.x, c01.y, c23.x, c23.y);
            ((float4*)C)[r * 16 + lc * 2 + 1] = make_float4(c45.x, c45.y, c67.x, c67.y);
        }
    }
}

// ---------------- 256-thread exclusive block scan ----------------
__device__ __forceinline__ int block_excl_scan_256(int v, int t, int* smem8) {
    unsigned lane = t & 31;
    int w = t >> 5;
    int x = v;
#pragma unroll
    for (int d = 1; d < 32; d <<= 1) {
        int y = __shfl_up_sync(0xffffffffu, x, d);
        if ((int)lane >= d) x += y;
    }
    if (lane == 31) smem8[w] = x;
    __syncthreads();
    if (t == 0) {
        int run = 0;
#pragma unroll
        for (int i = 0; i < 8; i++) { int c = smem8[i]; smem8[i] = run; run += c; }
    }
    __syncthreads();
    return x - v + smem8[w];
}

// -------- side #1: build B fragments + reset stats (1 block) --------------------
__global__ __launch_bounds__(256) void bf_kernel(const float* __restrict__ We) {
    int t = threadIdx.x;
    g_stats[t] = 0.0f;
    for (int i = t; i < 4096; i += 256) {
        int r = i & 1;
        int lane = (i >> 1) & 31;
        int nt = (i >> 6) & 7;
        int kt = (i >> 9) & 3;
        int term = (i >> 11) & 1;
        int gg = lane >> 2, tg = lane & 3;
        int n = nt * 8 + gg;
        int k0 = kt * 16 + 2 * tg + r * 8;
        float v0 = We[k0 * 64 + n];
        float v1 = We[(k0 + 1) * 64 + n];
        unsigned b0 = __float_as_uint(v0), b1 = __float_as_uint(v1);
        unsigned val;
        if (term == 0) {
            val = __byte_perm(b0, b1, 0x7632);
        } else {
            float h0 = __uint_as_float(b0 & 0xffff0000u);
            float h1 = __uint_as_float(b1 & 0xffff0000u);
            val = __byte_perm(__float_as_uint(v0 - h0), __float_as_uint(v1 - h1), 0x7632);
        }
        g_Bf[i] = val;
    }
}

// -------- side #2: V projection --------------------------------------------------
__global__ __launch_bounds__(128) void vproj_kernel(const float* __restrict__ x,
                                                    const float* __restrict__ Wv) {
    __shared__ float sW[4096];
    int t = threadIdx.x;
    stage_weight(sW, Wv, t, 128, 64);
    __syncthreads();
    gemm16_body(x, g_V, sW, blockIdx.x, t);
}

// -------- side #3: histogram dst degree + reset g_part ---------------------------
__global__ __launch_bounds__(256) void count_kernel(const int* __restrict__ ei) {
    int t = threadIdx.x;
    if (blockIdx.x == 0) g_part[t] = 0;
    int e = blockIdx.x * 256 + t;
    if (e < EE) atomicAdd(&g_cnt[ei[EE + e]], 1);
}

// -------- side #4: single-pass decoupled-lookback scan ---------------------------
__global__ __launch_bounds__(256) void scanlb_kernel() {
    __shared__ int s8[8];
    __shared__ int sTotal, sExc;
    int b = blockIdx.x, t = threadIdx.x;
    int i = b * 256 + t;
    int v = (i < NN) ? g_cnt[i] : 0;
    if (i < NN) g_cnt[i] = 0;   // reset for next graph replay
    int ex = block_excl_scan_256(v, t, s8);
    if (t == 255) sTotal = ex + v;
    __syncthreads();
    if (t == 0) {
        int total = sTotal;
        if (b == 0) {
            __threadfence();
            atomicExch(&g_part[0], (int)((2u << 30) | (unsigned)total));
            sExc = 0;
        } else {
            __threadfence();
            atomicExch(&g_part[b], (int)((1u << 30) | (unsigned)total));
            int running = 0;
            int look = b - 1;
            while (true) {
                unsigned w = (unsigned)atomicAdd(&g_part[look], 0);
                unsigned st = w >> 30;
                if (st == 0u) continue;
                running += (int)(w & 0x3fffffffu);
                if (st == 2u) break;
                look--;
            }
            __threadfence();
            atomicExch(&g_part[b], (int)((2u << 30) | (unsigned)(running + total)));
            sExc = running;
        }
    }
    __syncthreads();
    int off = ex + sExc;
    if (i < NN) { g_off[i] = off; g_cur[i] = off; }
    if (i == NN - 1) g_off[NN] = off + v;
}

// -------- side #5: bin edges by dst ----------------------------------------------
__global__ __launch_bounds__(256) void bin_kernel(const int* __restrict__ ei) {
    int e = blockIdx.x * 256 + threadIdx.x;
    if (e < EE) {
        int pos = atomicAdd(&g_cur[ei[EE + e]], 1);
        g_perm[pos] = e;
    }
}

// -------- main #1: Q/K projection; blockIdx.y = weight plane ---------------------
__global__ __launch_bounds__(128) void qk_kernel(const float* __restrict__ x,
                                                 const float* __restrict__ Wq,
                                                 const float* __restrict__ Wk) {
    __shared__ float sW[4096];
    int t = threadIdx.x;
    int wsel = blockIdx.y;
    const float* W = (wsel == 0) ? Wq : Wk;
    float* C = (wsel == 0) ? g_Q : g_K;
    stage_weight(sW, W, t, 128, 64);
    __syncthreads();
    gemm16_body(x, C, sW, blockIdx.x, t);
}

// -------- main #2 (profiled): mma.sync Eh GEMM, M-split, warp-private exchange ---
__global__ __launch_bounds__(128) void score_tc_kernel(const float* __restrict__ EA,
                                                       const int* __restrict__ ei) {
    __shared__ __align__(16) uint2 sBf[2][4][8][32];   // [term][kt][nt][lane], 16KB
    __shared__ __align__(16) float sX[64 * 68];        // half exchange tile, 17KB
    int t = threadIdx.x;
    int wid = t >> 5, lane = t & 31;
    int g = lane >> 2, tg = lane & 3;
    int lr = lane >> 3, lc = lane & 7;
    // stage B fragments
    {
        const uint4* src4 = (const uint4*)g_Bf;
        uint4* dst4 = (uint4*)sBf;
#pragma unroll
        for (int i = 0; i < 8; i++) dst4[t + i * 128] = src4[t + i * 128];
    }
    __syncthreads();

    const float2* A2 = (const float2*)EA;
    const float4* K4 = (const float4*)g_K;
    const float4* Q4 = (const float4*)g_Q;
    const float inv = 0.35355339059327373f;  // 1/sqrt(8)
    int ebase = blockIdx.x * 128 + wid * 32;

#pragma unroll
    for (int grp = 0; grp < 2; grp++) {
        int r0 = ebase + grp * 16 + g;
        float d[8][4] = {};
#pragma unroll
        for (int kt = 0; kt < 4; kt++) {
            float2 a00 = A2[r0 * 32 + kt * 8 + tg];
            float2 a01 = A2[r0 * 32 + kt * 8 + tg + 4];
            float2 a10 = A2[(r0 + 8) * 32 + kt * 8 + tg];
            float2 a11 = A2[(r0 + 8) * 32 + kt * 8 + tg + 4];
            unsigned ah[4], al[4];
            split2(a00, ah[0], al[0]);
            split2(a10, ah[1], al[1]);
            split2(a01, ah[2], al[2]);
            split2(a11, ah[3], al[3]);
#pragma unroll
            for (int nt = 0; nt < 8; nt++) {
                uint2 bh = sBf[0][kt][nt][lane];
                uint2 bl = sBf[1][kt][nt][lane];
                mma16816(d[nt], ah[0], ah[1], ah[2], ah[3], bh.x, bh.y);
                mma16816(d[nt], ah[0], ah[1], ah[2], ah[3], bl.x, bl.y);
                mma16816(d[nt], al[0], al[1], al[2], al[3], bh.x, bh.y);
            }
        }
        // prefetch edge endpoints for this group's scoring (overlap with exchange)
        int esrc[4], edst[4];
#pragma unroll
        for (int i = 0; i < 4; i++) {
            int e = ebase + grp * 16 + lr * 4 + i;
            esrc[i] = ei[e];
            edst[i] = ei[EE + e];
        }
        __syncwarp();   // previous scoring reads of this warp's sX rows done
        // exchange: warp-private tile rows wid*16 + {g, g+8}
        {
            int ra = wid * 16 + g;
#pragma unroll
            for (int nt = 0; nt < 8; nt++) {
                *(float2*)&sX[ra * 68 + nt * 8 + 2 * tg] = make_float2(d[nt][0], d[nt][1]);
                *(float2*)&sX[(ra + 8) * 68 + nt * 8 + 2 * tg] = make_float2(d[nt][2], d[nt][3]);
            }
        }
        __syncwarp();
        // scoring: lane (lr,lc): 4 edge rows x head lc
#pragma unroll
        for (int i = 0; i < 4; i++) {
            int el = wid * 16 + lr * 4 + i;
            int e = ebase + grp * 16 + lr * 4 + i;
            float4 ea = *(const float4*)&sX[el * 68 + lc * 8];
            float4 eb = *(const float4*)&sX[el * 68 + lc * 8 + 4];
            float4 kk0 = K4[esrc[i] * 16 + lc * 2], kk1 = K4[esrc[i] * 16 + lc * 2 + 1];
            float4 qq0 = Q4[edst[i] * 16 + lc * 2], qq1 = Q4[edst[i] * 16 + lc * 2 + 1];
            float s = ea.x * kk0.x * qq0.x + ea.y * kk0.y * qq0.y
                    + ea.z * kk0.z * qq0.z + ea.w * kk0.w * qq0.w
                    + eb.x * kk1.x * qq1.x + eb.y * kk1.y * qq1.y
                    + eb.z * kk1.z * qq1.z + eb.w * kk1.w * qq1.w;
            s = fminf(fmaxf(s * inv, -5.0f), 5.0f);
            g_sc[e * 8 + lc] = __expf(s);
        }
        __syncwarp();
    }
}

// -------- main #3 (after join): per-dst aggregation (no atomics) -----------------
__global__ __launch_bounds__(256) void agg_kernel(const int* __restrict__ ei) {
    int t = threadIdx.x;
    int w = t >> 5, lane = t & 31;
    int lr = lane >> 3, lc = lane & 7;
    int n = blockIdx.x * 8 + w;   // grid 6250 * 8 = 50000 exactly
    int beg = g_off[n], end = g_off[n + 1];
    const float4* V4 = (const float4*)g_V;
    float acc[8] = {0, 0, 0, 0, 0, 0, 0, 0};
    float zacc = 0.0f;
    for (int i = beg + lr; i < end; i += 4) {
        int e = g_perm[i];
        int src = ei[e];
        float s = g_sc[e * 8 + lc];
        float4 v0 = V4[src * 16 + lc * 2];
        float4 v1 = V4[src * 16 + lc * 2 + 1];
        acc[0] += v0.x * s; acc[1] += v0.y * s; acc[2] += v0.z * s; acc[3] += v0.w * s;
        acc[4] += v1.x * s; acc[5] += v1.y * s; acc[6] += v1.z * s; acc[7] += v1.w * s;
        zacc += s;
    }
#pragma unroll
    for (int j = 0; j < 8; j++) {
        acc[j] += __shfl_xor_sync(0xffffffffu, acc[j], 8);
        acc[j] += __shfl_xor_sync(0xffffffffu, acc[j], 16);
    }
    zacc += __shfl_xor_sync(0xffffffffu, zacc, 8);
    zacc += __shfl_xor_sync(0xffffffffu, zacc, 16);
    if (lr == 0) {
        float zi = 1.0f / (zacc + 1e-6f);
        ((float4*)g_wV)[n * 16 + lc * 2] =
            make_float4(acc[0] * zi, acc[1] * zi, acc[2] * zi, acc[3] * zi);
        ((float4*)g_wV)[n * 16 + lc * 2 + 1] =
            make_float4(acc[4] * zi, acc[5] * zi, acc[6] * zi, acc[7] * zi);
    }
}

// -------- main #4: O projection + residual -> g_h1, + BN1 stats ------------------
__global__ __launch_bounds__(128) void attn_out_kernel(const float* __restrict__ x,
                                                       const float* __restrict__ Ow,
                                                       const float* __restrict__ Ob) {
    __shared__ float sW[4096];
    __shared__ float ssum[64], ssq[64];
    int t = threadIdx.x;
    stage_weight(sW, Ow, t, 128, 64);
    if (t < 64) { ssum[t] = 0.0f; ssq[t] = 0.0f; }
    __syncthreads();
    int warp = t >> 5, lane = t & 31;
    int lr = lane >> 3, lc = lane & 7;
    int tile = blockIdx.x * 4 + warp;
    float ls[8] = {0, 0, 0, 0, 0, 0, 0, 0}, lq[8] = {0, 0, 0, 0, 0, 0, 0, 0};
    if (tile < (NN + 15) / 16) {
        int row0 = tile * 16 + lr * 4;
        const ulonglong2* sWu = (const ulonglong2*)sW;
        const float4* A4 = (const float4*)g_wV;
        unsigned long long acc[4][4] = {};
        for (int kc = 0; kc < 64; kc += 4) {
            float4 a[4];
#pragma unroll
            for (int i = 0; i < 4; i++) {
                int r = row0 + i;
                a[i] = (r < NN) ? A4[r * 16 + (kc >> 2)] : make_float4(0, 0, 0, 0);
            }
#pragma unroll
            for (int kk = 0; kk < 4; kk++) {
                ulonglong2 wlo = sWu[(kc + kk) * 16 + lc];
                ulonglong2 whi = sWu[(kc + kk) * 16 + 8 + lc];
#pragma unroll
                for (int i = 0; i < 4; i++) {
                    unsigned long long ax = pack2((&a[i].x)[kk]);
                    fma2(acc[i][0], wlo.x, ax);
                    fma2(acc[i][1], wlo.y, ax);
                    fma2(acc[i][2], whi.x, ax);
                    fma2(acc[i][3], whi.y, ax);
                }
            }
        }
        float4 ob0 = ((const float4*)Ob)[lc * 2];
        float4 ob1 = ((const float4*)Ob)[lc * 2 + 1];
        const float4* x4 = (const float4*)x;
#pragma unroll
        for (int i = 0; i < 4; i++) {
            int r = row0 + i;
            if (r < NN) {
                float2 c01 = unpack2(acc[i][0]), c23 = unpack2(acc[i][1]);
                float2 c45 = unpack2(acc[i][2]), c67 = unpack2(acc[i][3]);
                float4 xa = x4[r * 16 + lc * 2], xb = x4[r * 16 + lc * 2 + 1];
                float4 o0 = make_float4(c01.x + ob0.x + xa.x, c01.y + ob0.y + xa.y,
                                        c23.x + ob0.z + xa.z, c23.y + ob0.w + xa.w);
                float4 o1 = make_float4(c45.x + ob1.x + xb.x, c45.y + ob1.y + xb.y,
                                        c67.x + ob1.z + xb.z, c67.y + ob1.w + xb.w);
                ((float4*)g_h1)[r * 16 + lc * 2] = o0;
                ((float4*)g_h1)[r * 16 + lc * 2 + 1] = o1;
                ls[0] += o0.x; ls[1] += o0.y; ls[2] += o0.z; ls[3] += o0.w;
                ls[4] += o1.x; ls[5] += o1.y; ls[6] += o1.z; ls[7] += o1.w;
                lq[0] += o0.x * o0.x; lq[1] += o0.y * o0.y;
                lq[2] += o0.z * o0.z; lq[3] += o0.w * o0.w;
                lq[4] += o1.x * o1.x; lq[5] += o1.y * o1.y;
                lq[6] += o1.z * o1.z; lq[7] += o1.w * o1.w;
            }
        }
    }
#pragma unroll
    for (int j = 0; j < 8; j++) {
        atomicAdd(&ssum[lc * 8 + j], ls[j]);
        atomicAdd(&ssq[lc * 8 + j], lq[j]);
    }
    __syncthreads();
    if (t < 64) {
        atomicAdd(&g_stats[t], ssum[t]);
        atomicAdd(&g_stats[64 + t], ssq[t]);
    }
}

// -------- main #5: FUSED FFN: h2 = BN1h + (relu(BN1h@f1+b1))@f2 + b2 -------------
__global__ __launch_bounds__(128) void ffn_fused_kernel(const float* __restrict__ f1w,
                                                        const float* __restrict__ f1b,
                                                        const float* __restrict__ f2w,
                                                        const float* __restrict__ f2b,
                                                        const float* __restrict__ bn1g,
                                                        const float* __restrict__ bn1b) {
    __shared__ float sW1[2][4096];     // f1w swizzled halves, 32KB
    __shared__ float sT[16][132];      // hidden tile (padded rows)
    __shared__ float sH[16][68];       // BN1(h1) tile (padded rows)
    __shared__ float sScale[64], sShift[64], sB1[128], sF2b[64];
    __shared__ float ssum[64], ssq[64];
    int t = threadIdx.x;
    stage_weight_half(sW1[0], f1w, 0, t, 128);
    stage_weight_half(sW1[1], f1w, 1, t, 128);
    if (t < 64) {
        float mu = g_stats[t] * (1.0f / NN);
        float var = g_stats[64 + t] * (1.0f / NN) - mu * mu;
        float sc = bn1g[t] * rsqrtf(var + 1e-5f);
        sScale[t] = sc;
        sShift[t] = bn1b[t] - mu * sc;
        sF2b[t] = f2b[t];
        ssum[t] = 0.0f;
        ssq[t] = 0.0f;
    }
    if (t < 128) sB1[t] = f1b[t];
    __syncthreads();
    int row0 = blockIdx.x * 16;
#pragma unroll
    for (int ii = 0; ii < 8; ii++) {
        int idx = t + ii * 128;
        int rr = idx >> 6, c = idx & 63;
        float hv = g_h1[(row0 + rr) * 64 + c];
        sH[rr][c] = sScale[c] * hv + sShift[c];
    }
    __syncthreads();
    int w = t >> 5, lane = t & 31;
    int lr = lane >> 3, lc = lane & 7;
    int rh = w >> 1, ch = w & 1;
    int rb = rh * 8 + lr * 2;
    {
        const ulonglong2* sWu = (const ulonglong2*)sW1[ch];
        unsigned long long acc[2][4] = {};
        for (int kc = 0; kc < 64; kc += 4) {
            float4 a0 = *(const float4*)&sH[rb][kc];
            float4 a1 = *(const float4*)&sH[rb + 1][kc];
#pragma unroll
            for (int kk = 0; kk < 4; kk++) {
                ulonglong2 wlo = sWu[(kc + kk) * 16 + lc];
                ulonglong2 whi = sWu[(kc + kk) * 16 + 8 + lc];
                unsigned long long ax0 = pack2((&a0.x)[kk]);
                unsigned long long ax1 = pack2((&a1.x)[kk]);
                fma2(acc[0][0], wlo.x, ax0); fma2(acc[0][1], wlo.y, ax0);
                fma2(acc[0][2], whi.x, ax0); fma2(acc[0][3], whi.y, ax0);
                fma2(acc[1][0], wlo.x, ax1); fma2(acc[1][1], wlo.y, ax1);
                fma2(acc[1][2], whi.x, ax1); fma2(acc[1][3], whi.y, ax1);
            }
        }
        int j0 = ch * 64 + lc * 8;
        float4 b0 = *(const float4*)&sB1[j0];
        float4 b1 = *(const float4*)&sB1[j0 + 4];
#pragma unroll
        for (int i = 0; i < 2; i++) {
            float2 c01 = unpack2(acc[i][0]), c23 = unpack2(acc[i][1]);
            float2 c45 = unpack2(acc[i][2]), c67 = unpack2(acc[i][3]);
            float4 t0 = make_float4(fmaxf(c01.x + b0.x, 0.0f), fmaxf(c01.y + b0.y, 0.0f),
                                    fmaxf(c23.x + b0.z, 0.0f), fmaxf(c23.y + b0.w, 0.0f));
            float4 t1 = make_float4(fmaxf(c45.x + b1.x, 0.0f), fmaxf(c45.y + b1.y, 0.0f),
                                    fmaxf(c67.x + b1.z, 0.0f), fmaxf(c67.y + b1.w, 0.0f));
            *(float4*)&sT[rb + i][j0] = t0;
            *(float4*)&sT[rb + i][j0 + 4] = t1;
        }
    }
    __syncthreads();
    {
        int c4 = ch * 8 + lc;
        const ulonglong2* W2 = (const ulonglong2*)f2w;
        unsigned long long acc[2][2] = {};
        for (int kc = 0; kc < 128; kc += 4) {
            float4 a0 = *(const float4*)&sT[rb][kc];
            float4 a1 = *(const float4*)&sT[rb + 1][kc];
#pragma unroll
            for (int kk = 0; kk < 4; kk++) {
                ulonglong2 wv = W2[(kc + kk) * 16 + c4];
                unsigned long long ax0 = pack2((&a0.x)[kk]);
                unsigned long long ax1 = pack2((&a1.x)[kk]);
                fma2(acc[0][0], wv.x, ax0); fma2(acc[0][1], wv.y, ax0);
                fma2(acc[1][0], wv.x, ax1); fma2(acc[1][1], wv.y, ax1);
            }
        }
        int cb = c4 * 4;
        float2 fb0 = *(const float2*)&sF2b[cb];
        float2 fb1 = *(const float2*)&sF2b[cb + 2];
        float ls[4] = {0, 0, 0, 0}, lq[4] = {0, 0, 0, 0};
#pragma unroll
        for (int i = 0; i < 2; i++) {
            float2 c01 = unpack2(acc[i][0]), c23 = unpack2(acc[i][1]);
            float4 hres = *(const float4*)&sH[rb + i][cb];
            float4 o;
            o.x = c01.x + fb0.x + hres.x;
            o.y = c01.y + fb0.y + hres.y;
            o.z = c23.x + fb1.x + hres.z;
            o.w = c23.y + fb1.y + hres.w;
            *(float4*)&g_h2[(row0 + rb + i) * 64 + cb] = o;
            ls[0] += o.x; ls[1] += o.y; ls[2] += o.z; ls[3] += o.w;
            lq[0] += o.x * o.x; lq[1] += o.y * o.y;
            lq[2] += o.z * o.z; lq[3] += o.w * o.w;
        }
#pragma unroll
        for (int j = 0; j < 4; j++) {
            atomicAdd(&ssum[cb + j], ls[j]);
            atomicAdd(&ssq[cb + j], lq[j]);
        }
    }
    __syncthreads();
    if (t < 64) {
        atomicAdd(&g_stats[128 + t], ssum[t]);
        atomicAdd(&g_stats[192 + t], ssq[t]);
    }
}

// -------- main #6: BN2 apply -> output --------------------------------------------
__global__ __launch_bounds__(256) void bn2_kernel(const float* __restrict__ bn2g,
                                                  const float* __restrict__ bn2b,
                                                  float* __restrict__ out) {
    int tid = blockIdx.x * 256 + threadIdx.x;
    int i = tid & 15;
    int c0 = i * 4;
    float4 g = ((const float4*)bn2g)[i];
    float4 b = ((const float4*)bn2b)[i];
    float4 v = ((const float4*)g_h2)[tid];
    float4 o;
#pragma unroll
    for (int j = 0; j < 4; j++) {
        int c = c0 + j;
        float mu = g_stats[128 + c] * (1.0f / NN);
        float var = g_stats[192 + c] * (1.0f / NN) - mu * mu;
        float rs = rsqrtf(var + 1e-5f);
        (&o.x)[j] = (&g.x)[j] * ((&v.x)[j] - mu) * rs + (&b.x)[j];
    }
    ((float4*)out)[tid] = o;
}

// ---------------- host launcher (forked capture streams) ----------------
extern "C" void kernel_launch(void* const* d_in, const int* in_sizes, int n_in,
                              void* d_out, int out_size) {
    const float *x = nullptr, *edge_attr = nullptr;
    const float *Wq = nullptr, *Wk = nullptr, *We = nullptr, *Wv = nullptr, *Ow = nullptr;
    const float *Ob = nullptr, *f1w = nullptr, *f1b = nullptr, *f2w = nullptr, *f2b = nullptr;
    const float *bn1g = nullptr, *bn1b = nullptr, *bn2g = nullptr, *bn2b = nullptr;
    const int* ei = nullptr;
    int c4096 = 0, c8192 = 0, c64 = 0;
    for (int i = 0; i < n_in; i++) {
        int s = in_sizes[i];
        const void* p = d_in[i];
        if (s == NN * 64) x = (const float*)p;
        else if (s == EE * 64) edge_attr = (const float*)p;
        else if (s == 2 * EE) ei = (const int*)p;
        else if (s == 4096) {
            const float* f = (const float*)p;
            if (c4096 == 0) Wq = f;
            else if (c4096 == 1) Wk = f;
            else if (c4096 == 2) We = f;
            else if (c4096 == 3) Wv = f;
            else Ow = f;
            c4096++;
        } else if (s == 8192) {
            if (c8192 == 0) f1w = (const float*)p;
            else f2w = (const float*)p;
            c8192++;
        } else if (s == 128) {
            f1b = (const float*)p;
        } else if (s == 64) {
            const float* f = (const float*)p;
            if (c64 == 0) Ob = f;
            else if (c64 == 1) f2b = f;
            else if (c64 == 2) bn1g = f;
            else if (c64 == 3) bn1b = f;
            else if (c64 == 4) bn2g = f;
            else bn2b = f;
            c64++;
        }
    }

    static cudaStream_t s_side = nullptr;
    static cudaEvent_t s_ev0 = nullptr, s_evbf = nullptr, s_ev1 = nullptr;
    if (s_side == nullptr) {
        cudaStreamCreateWithFlags(&s_side, cudaStreamNonBlocking);
        cudaEventCreateWithFlags(&s_ev0, cudaEventDisableTiming);
        cudaEventCreateWithFlags(&s_evbf, cudaEventDisableTiming);
        cudaEventCreateWithFlags(&s_ev1, cudaEventDisableTiming);
    }

    // fork
    cudaEventRecord(s_ev0, 0);
    cudaStreamWaitEvent(s_side, s_ev0, 0);

    bf_kernel<<<1, 256, 0, s_side>>>(We);                       // #1 (side)
    cudaEventRecord(s_evbf, s_side);
    qk_kernel<<<dim3(782, 2), 128>>>(x, Wq, Wk);                // #2 (main)
    vproj_kernel<<<782, 128, 0, s_side>>>(x, Wv);               // #3 (side)
    cudaStreamWaitEvent(0, s_evbf, 0);                          // g_Bf ready
    score_tc_kernel<<<6250, 128>>>(edge_attr, ei);              // #4 (main) <- profiled
    count_kernel<<<(EE + 255) / 256, 256, 0, s_side>>>(ei);     // #5 (side)
    scanlb_kernel<<<196, 256, 0, s_side>>>();                   // #6 (side)
    bin_kernel<<<(EE + 255) / 256, 256, 0, s_side>>>(ei);       // #7 (side)
    cudaEventRecord(s_ev1, s_side);
    cudaStreamWaitEvent(0, s_ev1, 0);                           // V + CSR ready
    agg_kernel<<<6250, 256>>>(ei);                              // #8 (main)
    attn_out_kernel<<<782, 128>>>(x, Ow, Ob);                   // #9 (main)
    ffn_fused_kernel<<<3125, 128>>>(f1w, f1b, f2w, f2b, bn1g, bn1b);  // #10
    bn2_kernel<<<3125, 256>>>(bn2g, bn2b, (float*)d_out);       // #11
}